// round 5
// baseline (speedup 1.0000x reference)
#include <cuda_runtime.h>
#include <cstdint>

// LIF neuron scan: v = 0.5*v + x_t; spike = (v >= 1); v = spike ? 0 : v
// x: [T, B, D] f32, v0: [D] f32, out spikes: [T, B, D] f32.
//
// R5: phase-separated read/write macro-bursts to cut DRAM bus-turnaround loss.
// Ring = 24 cp.async stages, 3 groups of 8. Per iteration: 8-load burst
// (16KB/CTA) -> wait -> 8 compute steps buffering spikes in regs -> 8-store
// burst (16KB/CTA). Per-thread ring slots, no __syncthreads (positional
// wait_group ordering, 16-step slack).

#define LIF_CTA    128
#define LIF_GRID   148
#define LIF_BATCH  8
#define LIF_GROUPS 3
#define LIF_STAGES (LIF_BATCH * LIF_GROUPS)   // 24 slots -> 48 KB smem
#define LIF_TAU    0.5f

__global__ void __launch_bounds__(LIF_CTA, 1)
lif_scan_kernel(const float* __restrict__ x,
                const float* __restrict__ v0,
                float* __restrict__ out,
                int T, int N4, int D4, int chunk)
{
    __shared__ float4 ring[LIF_STAGES][LIF_CTA];

    const int chain = blockIdx.x * chunk + threadIdx.x;
    if (threadIdx.x >= chunk || chain >= N4) return;

    uint32_t slot0 = (uint32_t)__cvta_generic_to_shared(&ring[0][threadIdx.x]);
    const uint32_t stage_bytes = LIF_CTA * 16u;

    const char* gp = (const char*)x + (size_t)chain * 16u;
    const size_t gstride = (size_t)N4 * 16u;     // bytes per timestep

    // L2 evict-first for the read-once input stream
    uint64_t pol;
    asm volatile("createpolicy.fractional.L2::evict_first.b64 %0, 1.0;\n"
                 : "=l"(pol));

    // ---- prologue: fill GROUPS-1 = 2 groups (16 stages) ----
    #pragma unroll
    for (int g = 0; g < LIF_GROUPS - 1; g++) {
        #pragma unroll
        for (int j = 0; j < LIF_BATCH; j++) {
            uint32_t dst = slot0 + (uint32_t)(g * LIF_BATCH + j) * stage_bytes;
            asm volatile(
                "cp.async.cg.shared.global.L2::cache_hint [%0], [%1], 16, %2;\n"
                :: "r"(dst), "l"(gp), "l"(pol) : "memory");
            gp += gstride;
        }
        asm volatile("cp.async.commit_group;\n" ::: "memory");
    }

    // initial membrane potential: v0[d] broadcast over batch
    float4 v = ((const float4*)v0)[chain % D4];

    float4* op = (float4*)out + chain;

    int wgrp = LIF_GROUPS - 1;   // ring group to write next
    int rgrp = 0;                // ring group to read next

    const int prefetched = (LIF_GROUPS - 1) * LIF_BATCH;   // 16 steps

    for (int t = 0; t < T; t += LIF_BATCH) {
        // ---- read burst: 8 cp.asyncs for steps t+16..t+23 (if any) ----
        // ALWAYS commit one group per iteration (positional accounting)
        if (t + prefetched < T) {
            #pragma unroll
            for (int j = 0; j < LIF_BATCH; j++) {
                uint32_t dst = slot0 +
                    (uint32_t)(wgrp * LIF_BATCH + j) * stage_bytes;
                asm volatile(
                    "cp.async.cg.shared.global.L2::cache_hint [%0], [%1], 16, %2;\n"
                    :: "r"(dst), "l"(gp), "l"(pol) : "memory");
                gp += gstride;
            }
        }
        asm volatile("cp.async.commit_group;\n" ::: "memory");
        if (++wgrp == LIF_GROUPS) wgrp = 0;

        // all but the 2 most recent groups complete -> this batch landed
        asm volatile("cp.async.wait_group %0;\n" :: "n"(LIF_GROUPS - 1) : "memory");

        // ---- compute burst: 8 steps, spikes buffered in registers ----
        float4 sp[LIF_BATCH];
        #pragma unroll
        for (int j = 0; j < LIF_BATCH; j++) {
            float4 xt;
            uint32_t src = slot0 +
                (uint32_t)(rgrp * LIF_BATCH + j) * stage_bytes;
            asm volatile("ld.shared.v4.f32 {%0,%1,%2,%3}, [%4];\n"
                         : "=f"(xt.x), "=f"(xt.y), "=f"(xt.z), "=f"(xt.w)
                         : "r"(src));

            v.x = fmaf(LIF_TAU, v.x, xt.x);
            v.y = fmaf(LIF_TAU, v.y, xt.y);
            v.z = fmaf(LIF_TAU, v.z, xt.z);
            v.w = fmaf(LIF_TAU, v.w, xt.w);
            bool fx = v.x >= 1.0f, fy = v.y >= 1.0f,
                 fz = v.z >= 1.0f, fw = v.w >= 1.0f;
            sp[j].x = fx ? 1.0f : 0.0f;  v.x = fx ? 0.0f : v.x;
            sp[j].y = fy ? 1.0f : 0.0f;  v.y = fy ? 0.0f : v.y;
            sp[j].z = fz ? 1.0f : 0.0f;  v.z = fz ? 0.0f : v.z;
            sp[j].w = fw ? 1.0f : 0.0f;  v.w = fw ? 0.0f : v.w;
        }
        if (++rgrp == LIF_GROUPS) rgrp = 0;

        // ---- write burst: 8 back-to-back STG.128 ----
        #pragma unroll
        for (int j = 0; j < LIF_BATCH; j++) {
            __stcs(op, sp[j]);
            op += N4;
        }
    }
}

extern "C" void kernel_launch(void* const* d_in, const int* in_sizes, int n_in,
                              void* d_out, int out_size)
{
    const float* x  = (const float*)d_in[0];   // [T, B, D]
    const float* v0 = (const float*)d_in[1];   // [D]
    float* out = (float*)d_out;

    const int T = 512;                 // fixed by problem setup
    const int total = in_sizes[0];     // T*B*D
    const int D = in_sizes[1];
    const int N  = total / T;          // B*D
    const int N4 = N / 4;
    const int D4 = D / 4;

    // Spread chains over all 148 SMs; chains per CTA capped at CTA size.
    int chunk = (N4 + LIF_GRID - 1) / LIF_GRID;
    if (chunk > LIF_CTA) chunk = LIF_CTA;
    int grid = (N4 + chunk - 1) / chunk;

    lif_scan_kernel<<<grid, LIF_CTA>>>(x, v0, out, T, N4, D4, chunk);
}